// round 10
// baseline (speedup 1.0000x reference)
#include <cuda_runtime.h>

// Problem shape (fixed by the dataset)
constexpr int C = 32, D = 64, H = 192, W = 160;
constexpr int HW  = H * W;        // 30720
constexpr int DHW = D * H * W;    // 1,966,080

// Block: 64 threads along d (full D), 4 spatial columns (w) per block.
// Grid: (W/4, H). Warp = 32 consecutive d for one (w,h) -> coalesced stores.
__global__ __launch_bounds__(256, 4)
void affine_grid_sample_kernel(const float* __restrict__ in,
                               const float* __restrict__ theta,
                               float* __restrict__ out)
{
    const int d = threadIdx.x;                       // 0..63
    const int w = blockIdx.x * 4 + threadIdx.y;      // 0..159
    const int h = blockIdx.y;                        // 0..191

    // ---- affine grid (align_corners=True linspace) ----
    const float xn = -1.0f + 2.0f * (float)w / (float)(W - 1);
    const float yn = -1.0f + 2.0f * (float)h / (float)(H - 1);
    const float zn = -1.0f + 2.0f * (float)d / (float)(D - 1);

    float t[12];
#pragma unroll
    for (int i = 0; i < 12; i++) t[i] = __ldg(theta + i);

    const float gx = t[0] * xn + t[1] * yn + t[2]  * zn + t[3];
    const float gy = t[4] * xn + t[5] * yn + t[6]  * zn + t[7];
    const float gz = t[8] * xn + t[9] * yn + t[10] * zn + t[11];

    // ---- pixel coords (align_corners=True) ----
    const float px = (gx + 1.0f) * 0.5f * (float)(W - 1);
    const float py = (gy + 1.0f) * 0.5f * (float)(H - 1);
    const float pz = (gz + 1.0f) * 0.5f * (float)(D - 1);

    const float fx = floorf(px), fy = floorf(py), fz = floorf(pz);
    const int x0 = (int)fx, y0 = (int)fy, z0 = (int)fz;
    const int x1 = x0 + 1,  y1 = y0 + 1,  z1 = z0 + 1;
    const float wx = px - fx, wy = py - fy, wz = pz - fz;

    // Per-axis weights folded with validity (zeros padding): corner validity
    // factorizes as vx*vy*vz, so masking each axis weight is exact.
    const float ax0 = (x0 >= 0 && x0 < W) ? (1.0f - wx) : 0.0f;
    const float ax1 = (x1 >= 0 && x1 < W) ? wx          : 0.0f;
    const float ay0 = (y0 >= 0 && y0 < H) ? (1.0f - wy) : 0.0f;
    const float ay1 = (y1 >= 0 && y1 < H) ? wy          : 0.0f;
    const float az0 = (z0 >= 0 && z0 < D) ? (1.0f - wz) : 0.0f;
    const float az1 = (z1 >= 0 && z1 < D) ? wz          : 0.0f;

    // Clamped indices (safe reads; masked weights make OOB contributions 0)
    const int xc0 = min(max(x0, 0), W - 1);
    const int xc1 = min(max(x1, 0), W - 1);
    const int yc0 = min(max(y0, 0), H - 1);
    const int yc1 = min(max(y1, 0), H - 1);
    const int zc0 = min(max(z0, 0), D - 1);
    const int zc1 = min(max(z1, 0), D - 1);

    // 4 (z,y) row bases; x offsets added per corner
    const int r00 = (zc0 * H + yc0) * W;
    const int r01 = (zc0 * H + yc1) * W;
    const int r10 = (zc1 * H + yc0) * W;
    const int r11 = (zc1 * H + yc1) * W;

    // Full 8-corner weights
    const float c000 = az0 * ay0 * ax0;
    const float c001 = az0 * ay0 * ax1;
    const float c010 = az0 * ay1 * ax0;
    const float c011 = az0 * ay1 * ax1;
    const float c100 = az1 * ay0 * ax0;
    const float c101 = az1 * ay0 * ax1;
    const float c110 = az1 * ay1 * ax0;
    const float c111 = az1 * ay1 * ax1;

    // Output: [N,W,H,C,D] -> (((w*H + h)*C + c)*D + d)
    float* op = out + ((size_t)(w * H + h) * C) * D + d;
    const float* ip = in;

#pragma unroll 4
    for (int c = 0; c < C; c++) {
        const float v000 = __ldg(ip + r00 + xc0);
        const float v001 = __ldg(ip + r00 + xc1);
        const float v010 = __ldg(ip + r01 + xc0);
        const float v011 = __ldg(ip + r01 + xc1);
        const float v100 = __ldg(ip + r10 + xc0);
        const float v101 = __ldg(ip + r10 + xc1);
        const float v110 = __ldg(ip + r11 + xc0);
        const float v111 = __ldg(ip + r11 + xc1);

        float r = c000 * v000;
        r = fmaf(c001, v001, r);
        r = fmaf(c010, v010, r);
        r = fmaf(c011, v011, r);
        r = fmaf(c100, v100, r);
        r = fmaf(c101, v101, r);
        r = fmaf(c110, v110, r);
        r = fmaf(c111, v111, r);

        op[(size_t)c * D] = r;
        ip += DHW;  // next channel
    }
}

extern "C" void kernel_launch(void* const* d_in, const int* in_sizes, int n_in,
                              void* d_out, int out_size)
{
    const float* in    = (const float*)d_in[0];   // [1,32,64,192,160]
    const float* theta = (const float*)d_in[1];   // [12]
    float* out = (float*)d_out;                   // [1,160,192,32,64]

    dim3 block(64, 4);           // d x (w group)
    dim3 grid(W / 4, H);         // 40 x 192
    affine_grid_sample_kernel<<<grid, block>>>(in, theta, out);
}

// round 11
// speedup vs baseline: 3.7575x; 3.7575x over previous
#include <cuda_runtime.h>

constexpr int C = 32, D = 64, H = 192, W = 160;
constexpr int DHW = D * H * W;     // 1,966,080

constexpr int W_T = 32;            // tile width  (w)
constexpr int D_T = 32;            // tile depth  (d)
constexpr int PTS = D_T / 8;       // d-points per thread = 4

// Block: 32 (w) x 8 (d-rows) = 256 threads.
// Compute phase: lanes along w  -> coalesced input reads.
// Write phase:   lanes along d  -> coalesced output writes (via smem transpose).
__global__ __launch_bounds__(256, 2)
void affine_grid_sample_kernel(const float* __restrict__ in,
                               const float* __restrict__ theta,
                               float* __restrict__ out)
{
    __shared__ float s[2][W_T][D_T + 1];   // +1 pad: conflict-free both phases

    const int wl = threadIdx.x;                 // 0..31 (w within tile)
    const int ty = threadIdx.y;                 // 0..7
    const int w  = blockIdx.x * W_T + wl;       // 0..159
    const int d0 = blockIdx.y * D_T;            // 0 or 32
    const int h  = blockIdx.z;                  // 0..191

    float t[12];
#pragma unroll
    for (int i = 0; i < 12; i++) t[i] = __ldg(theta + i);

    const float xn = -1.0f + 2.0f * (float)w / (float)(W - 1);
    const float yn = -1.0f + 2.0f * (float)h / (float)(H - 1);

    // Per-point geometry, held in registers across the channel loop.
    int   adr[PTS][4];      // 4 (z,y)-row bases with xc0 folded in
    int   dx[PTS];          // xc1 - xc0 (0 at clamped edges, else 1)
    float zy[PTS][4];       // az*ay products for the 4 rows
    float ax0[PTS], ax1[PTS];

#pragma unroll
    for (int p = 0; p < PTS; p++) {
        const int d  = d0 + ty + 8 * p;
        const float zn = -1.0f + 2.0f * (float)d / (float)(D - 1);

        const float gx = t[0] * xn + t[1] * yn + t[2]  * zn + t[3];
        const float gy = t[4] * xn + t[5] * yn + t[6]  * zn + t[7];
        const float gz = t[8] * xn + t[9] * yn + t[10] * zn + t[11];

        const float px = (gx + 1.0f) * 0.5f * (float)(W - 1);
        const float py = (gy + 1.0f) * 0.5f * (float)(H - 1);
        const float pz = (gz + 1.0f) * 0.5f * (float)(D - 1);

        const float fx = floorf(px), fy = floorf(py), fz = floorf(pz);
        const int x0 = (int)fx, y0 = (int)fy, z0 = (int)fz;
        const int x1 = x0 + 1,  y1 = y0 + 1,  z1 = z0 + 1;
        const float wx = px - fx, wy = py - fy, wz = pz - fz;

        // Validity folded into per-axis weights (zeros padding is separable).
        const float vx0 = (x0 >= 0 && x0 < W) ? (1.0f - wx) : 0.0f;
        const float vx1 = (x1 >= 0 && x1 < W) ? wx          : 0.0f;
        const float vy0 = (y0 >= 0 && y0 < H) ? (1.0f - wy) : 0.0f;
        const float vy1 = (y1 >= 0 && y1 < H) ? wy          : 0.0f;
        const float vz0 = (z0 >= 0 && z0 < D) ? (1.0f - wz) : 0.0f;
        const float vz1 = (z1 >= 0 && z1 < D) ? wz          : 0.0f;

        const int xc0 = min(max(x0, 0), W - 1);
        const int xc1 = min(max(x1, 0), W - 1);
        const int yc0 = min(max(y0, 0), H - 1);
        const int yc1 = min(max(y1, 0), H - 1);
        const int zc0 = min(max(z0, 0), D - 1);
        const int zc1 = min(max(z1, 0), D - 1);

        adr[p][0] = (zc0 * H + yc0) * W + xc0;
        adr[p][1] = (zc0 * H + yc1) * W + xc0;
        adr[p][2] = (zc1 * H + yc0) * W + xc0;
        adr[p][3] = (zc1 * H + yc1) * W + xc0;
        dx[p]     = xc1 - xc0;

        zy[p][0] = vz0 * vy0;
        zy[p][1] = vz0 * vy1;
        zy[p][2] = vz1 * vy0;
        zy[p][3] = vz1 * vy1;
        ax0[p] = vx0;
        ax1[p] = vx1;
    }

    // Output base pointers for the write phase (lanes along d).
    // out[((w*H + h)*C + c)*D + d]
    float* outp[PTS];
#pragma unroll
    for (int p = 0; p < PTS; p++) {
        const int ow = blockIdx.x * W_T + ty + 8 * p;   // w handled in write phase
        outp[p] = out + ((size_t)(ow * H + h) * C) * (size_t)D + d0 + wl;
    }

    const float* ip = in;
    for (int c = 0; c < C; c++) {
        const int buf = c & 1;

        // ---- compute phase: lanes along w, coalesced reads ----
#pragma unroll
        for (int p = 0; p < PTS; p++) {
            const int a0 = adr[p][0], a1 = adr[p][1];
            const int a2 = adr[p][2], a3 = adr[p][3];
            const int dd = dx[p];

            const float v00 = __ldg(ip + a0);
            const float v01 = __ldg(ip + a0 + dd);
            const float v10 = __ldg(ip + a1);
            const float v11 = __ldg(ip + a1 + dd);
            const float v20 = __ldg(ip + a2);
            const float v21 = __ldg(ip + a2 + dd);
            const float v30 = __ldg(ip + a3);
            const float v31 = __ldg(ip + a3 + dd);

            float r;
            r =          zy[p][0] * fmaf(ax1[p], v01, ax0[p] * v00);
            r = fmaf(zy[p][1], fmaf(ax1[p], v11, ax0[p] * v10), r);
            r = fmaf(zy[p][2], fmaf(ax1[p], v21, ax0[p] * v20), r);
            r = fmaf(zy[p][3], fmaf(ax1[p], v31, ax0[p] * v30), r);

            s[buf][wl][ty + 8 * p] = r;
        }

        __syncthreads();   // buf ready; also guarantees prior write phase done

        // ---- write phase: lanes along d, coalesced 128B stores ----
        const size_t co = (size_t)c * D;
#pragma unroll
        for (int p = 0; p < PTS; p++) {
            outp[p][co] = s[buf][ty + 8 * p][wl];
        }

        ip += DHW;
    }
}

extern "C" void kernel_launch(void* const* d_in, const int* in_sizes, int n_in,
                              void* d_out, int out_size)
{
    const float* in    = (const float*)d_in[0];   // [1,32,64,192,160]
    const float* theta = (const float*)d_in[1];   // [12]
    float* out = (float*)d_out;                   // [1,160,192,32,64]

    dim3 block(32, 8);                   // w x d-rows
    dim3 grid(W / W_T, D / D_T, H);      // 5 x 2 x 192 = 1920 blocks
    affine_grid_sample_kernel<<<grid, block>>>(in, theta, out);
}

// round 12
// speedup vs baseline: 4.5025x; 1.1983x over previous
#include <cuda_runtime.h>

constexpr int C = 32, D = 64, H = 192, W = 160;
constexpr int DHW = D * H * W;     // 1,966,080

constexpr int W_T = 32;            // tile width (w)
constexpr int D_T = 16;            // tile depth (d)
constexpr int PTS = 2;             // d-points per thread (D_T / 8)
constexpr int SP  = D_T + 1;       // padded smem row (17 -> conflict-free STS)

// Block: 32 (w) x 8 (d-rows) = 256 threads, 2 points each -> 32x16 tile.
// Compute: lanes along w (coalesced reads). Write: transpose via smem,
// stores contiguous in d. 2 channels per barrier, 4-buffer smem ring.
__global__ __launch_bounds__(256, 4)
void affine_grid_sample_kernel(const float* __restrict__ in,
                               const float* __restrict__ theta,
                               float* __restrict__ out)
{
    __shared__ float s[4][W_T][SP];

    const int wl = threadIdx.x;                 // 0..31
    const int ty = threadIdx.y;                 // 0..7
    const int w  = blockIdx.x * W_T + wl;       // 0..159
    const int d0 = blockIdx.y * D_T;            // 0,16,32,48
    const int h  = blockIdx.z;                  // 0..191

    float t[12];
#pragma unroll
    for (int i = 0; i < 12; i++) t[i] = __ldg(theta + i);

    const float xn = -1.0f + 2.0f * (float)w / (float)(W - 1);
    const float yn = -1.0f + 2.0f * (float)h / (float)(H - 1);

    // Per-point geometry held in registers across the channel loop.
    int   adr[PTS][4];       // 4 (z,y)-row bases with xc0 folded in
    int   dx[PTS];           // xc1-xc0 (0 at clamped edge, else 1)
    float zy[PTS][4];        // masked az*ay products
    float ax0[PTS], ax1[PTS];

#pragma unroll
    for (int p = 0; p < PTS; p++) {
        const int d = d0 + ty + 8 * p;
        const float zn = -1.0f + 2.0f * (float)d / (float)(D - 1);

        const float gx = t[0] * xn + t[1] * yn + t[2]  * zn + t[3];
        const float gy = t[4] * xn + t[5] * yn + t[6]  * zn + t[7];
        const float gz = t[8] * xn + t[9] * yn + t[10] * zn + t[11];

        const float px = (gx + 1.0f) * 0.5f * (float)(W - 1);
        const float py = (gy + 1.0f) * 0.5f * (float)(H - 1);
        const float pz = (gz + 1.0f) * 0.5f * (float)(D - 1);

        const float fx = floorf(px), fy = floorf(py), fz = floorf(pz);
        const int x0 = (int)fx, y0 = (int)fy, z0 = (int)fz;
        const int x1 = x0 + 1,  y1 = y0 + 1,  z1 = z0 + 1;
        const float wx = px - fx, wy = py - fy, wz = pz - fz;

        const float vx0 = (x0 >= 0 && x0 < W) ? (1.0f - wx) : 0.0f;
        const float vx1 = (x1 >= 0 && x1 < W) ? wx          : 0.0f;
        const float vy0 = (y0 >= 0 && y0 < H) ? (1.0f - wy) : 0.0f;
        const float vy1 = (y1 >= 0 && y1 < H) ? wy          : 0.0f;
        const float vz0 = (z0 >= 0 && z0 < D) ? (1.0f - wz) : 0.0f;
        const float vz1 = (z1 >= 0 && z1 < D) ? wz          : 0.0f;

        const int xc0 = min(max(x0, 0), W - 1);
        const int xc1 = min(max(x1, 0), W - 1);
        const int yc0 = min(max(y0, 0), H - 1);
        const int yc1 = min(max(y1, 0), H - 1);
        const int zc0 = min(max(z0, 0), D - 1);
        const int zc1 = min(max(z1, 0), D - 1);

        adr[p][0] = (zc0 * H + yc0) * W + xc0;
        adr[p][1] = (zc0 * H + yc1) * W + xc0;
        adr[p][2] = (zc1 * H + yc0) * W + xc0;
        adr[p][3] = (zc1 * H + yc1) * W + xc0;
        dx[p]     = xc1 - xc0;

        zy[p][0] = vz0 * vy0;
        zy[p][1] = vz0 * vy1;
        zy[p][2] = vz1 * vy0;
        zy[p][3] = vz1 * vy1;
        ax0[p] = vx0;
        ax1[p] = vx1;
    }

    // Write-phase mapping: per (k, buf) pass, thread covers
    //   w_row = k*16 + ty*2 + (wl>>4),  dl = wl & 15
    const int w_rA = ty * 2 + (wl >> 4);          // k=0 row
    const int dl   = wl & 15;
    const size_t obaseA = ((size_t)((blockIdx.x * W_T + w_rA) * H + h) * C) * D + d0 + dl;
    const size_t obaseB = ((size_t)((blockIdx.x * W_T + w_rA + 16) * H + h) * C) * D + d0 + dl;

    const float* ip = in;
    for (int c = 0; c < C; c += 2) {
        const int b0 = c & 3;          // buffers b0, b0+1

        // ---- compute 2 channels (lanes along w, coalesced reads) ----
#pragma unroll
        for (int ch = 0; ch < 2; ch++) {
            const float* ipc = ip + ch * DHW;
#pragma unroll
            for (int p = 0; p < PTS; p++) {
                const int a0 = adr[p][0], a1 = adr[p][1];
                const int a2 = adr[p][2], a3 = adr[p][3];
                const int dd = dx[p];

                const float v00 = __ldg(ipc + a0);
                const float v01 = __ldg(ipc + a0 + dd);
                const float v10 = __ldg(ipc + a1);
                const float v11 = __ldg(ipc + a1 + dd);
                const float v20 = __ldg(ipc + a2);
                const float v21 = __ldg(ipc + a2 + dd);
                const float v30 = __ldg(ipc + a3);
                const float v31 = __ldg(ipc + a3 + dd);

                float r;
                r =          zy[p][0] * fmaf(ax1[p], v01, ax0[p] * v00);
                r = fmaf(zy[p][1], fmaf(ax1[p], v11, ax0[p] * v10), r);
                r = fmaf(zy[p][2], fmaf(ax1[p], v21, ax0[p] * v20), r);
                r = fmaf(zy[p][3], fmaf(ax1[p], v31, ax0[p] * v30), r);

                s[b0 + ch][wl][ty + 8 * p] = r;
            }
        }

        __syncthreads();   // bufs ready; also fences reuse of these bufs

        // ---- write phase: 4 stores/thread, contiguous in d ----
#pragma unroll
        for (int ch = 0; ch < 2; ch++) {
            const size_t co = (size_t)(c + ch) * D;
            out[obaseA + co] = s[b0 + ch][w_rA][dl];
            out[obaseB + co] = s[b0 + ch][w_rA + 16][dl];
        }

        ip += 2 * DHW;
    }
}

extern "C" void kernel_launch(void* const* d_in, const int* in_sizes, int n_in,
                              void* d_out, int out_size)
{
    const float* in    = (const float*)d_in[0];   // [1,32,64,192,160]
    const float* theta = (const float*)d_in[1];   // [12]
    float* out = (float*)d_out;                   // [1,160,192,32,64]

    dim3 block(32, 8);                    // w x d-rows
    dim3 grid(W / W_T, D / D_T, H);       // 5 x 4 x 192 = 3840
    affine_grid_sample_kernel<<<grid, block>>>(in, theta, out);
}